// round 11
// baseline (speedup 1.0000x reference)
#include <cuda_runtime.h>
#include <cstdint>
#include <math.h>

#define NN 16
#define TT 800
#define FF 90
#define SS 128
#define LL 200
#define NEGF (-1e30f)

// per-utterance scores scratch (device globals: no allocation allowed)
__device__ float g_den[NN];
__device__ float g_num[NN];

// ---- packed fp32x2 helpers (sm_103a) ----
__device__ __forceinline__ unsigned long long fma_f32x2(unsigned long long a,
                                                        unsigned long long b,
                                                        unsigned long long c) {
    unsigned long long d;
    asm("fma.rn.f32x2 %0, %1, %2, %3;" : "=l"(d) : "l"(a), "l"(b), "l"(c));
    return d;
}
__device__ __forceinline__ unsigned long long add_f32x2(unsigned long long a,
                                                        unsigned long long b) {
    unsigned long long d;
    asm("add.rn.f32x2 %0, %1, %2;" : "=l"(d) : "l"(a), "l"(b));
    return d;
}
__device__ __forceinline__ unsigned long long pack2(float lo, float hi) {
    unsigned long long d;
    asm("mov.b64 %0, {%1, %2};" : "=l"(d) : "f"(lo), "f"(hi));
    return d;
}
__device__ __forceinline__ float2 unpack2(unsigned long long v) {
    float lo, hi;
    asm("mov.b64 {%0, %1}, %2;" : "=f"(lo), "=f"(hi) : "l"(v));
    return make_float2(lo, hi);
}

#define BAR_SYNC(id, cnt) \
    asm volatile("bar.sync %0, %1;" :: "r"(id), "r"(cnt) : "memory")

// blocks 0..7:   den CTA, 256 threads = 2 independent 128-thread groups,
//                group g runs utterance b + 8g (own named barrier, own sh_v).
//                One full state column per thread; groups hide each other's
//                exposed latency on the shared SMSPs.
// blocks 8..23:  num for utterance b-8. 128 threads, 2 chain states/thread.
__global__ __launch_bounds__(256, 1)
void mmi_forward(const float* __restrict__ nnet,   // [N, T, F] log-softmax
                 const int*   __restrict__ sup,    // [N, 3]
                 const float* __restrict__ trans,  // [S, S]
                 const int*   __restrict__ dlab,   // [S]
                 const int*   __restrict__ nlab,   // [N, L]
                 const int*   __restrict__ nlens)  // [N]
{
    __shared__ __align__(16) float sh_v[2][2][SS];   // [group][buf][state]
    __shared__ float sh_wsum[2][4];
    __shared__ float sh_a[2][LL + 8];

    const int tid = threadIdx.x;
    const int b   = blockIdx.x;

    if (b < 8) {
        // ======= denominator forward (scaled linear space), dual utterance ====
        const int g  = tid >> 7;            // warp-group 0 or 1
        const int lt = tid & 127;           // lane within group
        const int n  = b + 8 * g;           // utterance for this group
        const int nf = sup[n * 3 + 2];
        const int s  = lt;                  // output state
        const int barid = g + 1;

        // Full E column (128 k-values) in registers, packed f32x2 (128 regs).
        unsigned long long E2[64];
        #pragma unroll 8
        for (int j = 0; j < 64; ++j) {
            E2[j] = pack2(expf(trans[(2 * j) * SS + s]),
                          expf(trans[(2 * j + 1) * SS + s]));
        }
        const int lab = dlab[s];
        const float* lp_base = nnet + (long long)n * TT * FF + lab;
        float lp  = __ldg(lp_base);                          // t = 0
        float lp1 = __ldg(lp_base + FF);                     // t = 1

        sh_v[g][0][s] = (s == 0) ? 1.0f : 0.0f;
        BAR_SYNC(barid, 128);

        int cur  = 0;
        int Mexp = 0;

        #pragma unroll 2
        for (int t = 0; t < nf; ++t) {
            // exact 2^-e rescale keyed to v[0]'s exponent, on even steps only
            float ps;
            if ((t & 1) == 0) {
                const float v0 = sh_v[g][cur][0];
                const int   eb = (int)(__float_as_uint(v0) >> 23);  // biased exp
                Mexp += eb - 127;
                ps = __expf(lp) *
                     __uint_as_float((unsigned)(254 - eb) << 23);
            } else {
                ps = __expf(lp);
            }

            const int   tn   = (t + 2 < TT) ? (t + 2) : (TT - 1);
            const float lpn2 = __ldg(lp_base + (long long)tn * FF); // prefetch d=2

            const ulonglong2* vp =
                reinterpret_cast<const ulonglong2*>(&sh_v[g][cur][0]);

            // 64 FFMA2 across 4 accumulators, q loaded in 2 chunks of 16
            unsigned long long a0 = 0ull, a1 = 0ull, a2 = 0ull, a3 = 0ull;
            #pragma unroll
            for (int gg = 0; gg < 2; ++gg) {
                ulonglong2 q[16];
                #pragma unroll
                for (int i = 0; i < 16; ++i) q[i] = vp[16 * gg + i];
                #pragma unroll
                for (int i = 0; i < 8; ++i) {
                    a0 = fma_f32x2(q[2 * i].x,     E2[32 * gg + 4 * i + 0], a0);
                    a1 = fma_f32x2(q[2 * i].y,     E2[32 * gg + 4 * i + 1], a1);
                    a2 = fma_f32x2(q[2 * i + 1].x, E2[32 * gg + 4 * i + 2], a2);
                    a3 = fma_f32x2(q[2 * i + 1].y, E2[32 * gg + 4 * i + 3], a3);
                }
            }
            a0 = add_f32x2(a0, a2);
            a1 = add_f32x2(a1, a3);
            a0 = add_f32x2(a0, a1);
            const float2 u = unpack2(a0);
            const float dot = u.x + u.y;

            sh_v[g][cur ^ 1][s] = dot * ps;
            lp  = lp1;
            lp1 = lpn2;
            BAR_SYNC(barid, 128);
            cur ^= 1;
        }

        // den = Mexp*ln2 + log(sum v)
        {
            float v = sh_v[g][cur][s];
            #pragma unroll
            for (int o = 16; o; o >>= 1) v += __shfl_xor_sync(0xffffffffu, v, o);
            if ((lt & 31) == 0) sh_wsum[g][lt >> 5] = v;
        }
        BAR_SYNC(barid, 128);
        if (lt == 0) {
            const float sv = sh_wsum[g][0] + sh_wsum[g][1] +
                             sh_wsum[g][2] + sh_wsum[g][3];
            g_den[n] = (float)((double)Mexp * 0.6931471805599453 +
                               (double)logf(sv));
        }
    } else {
        // ============ numerator forward (log space), 2 states/thread ==========
        const int n  = b - 8;
        const int nf = sup[n * 3 + 2];
        const int qi = nlens[n];
        const int i  = tid;                 // 0..127; active i < 100
        if (tid >= 128) return;             // num CTAs launched with 128, safe

        // thread i owns states l0 = 2i+1 and l1 = 2i+2
        const float* lpb0 = nnet;  // dummy init
        const float* lpb1 = nnet;
        float lpA = 0.f, lpA1 = 0.f, lpB = 0.f, lpB1 = 0.f;

        if (i < 100) {
            const long long base = (long long)n * TT * FF;
            lpb0 = nnet + base + nlab[n * LL + 2 * i];       // emit for l0
            lpb1 = nnet + base + nlab[n * LL + 2 * i + 1];   // emit for l1
            lpA  = __ldg(lpb0);       lpB  = __ldg(lpb1);
            lpA1 = __ldg(lpb0 + FF);  lpB1 = __ldg(lpb1 + FF);
        }
        for (int j = i; j <= LL; j += 128) {
            sh_a[0][j] = (j == 0) ? 0.0f : NEGF;
            sh_a[1][j] = NEGF;
        }
        int cur = 0;
        BAR_SYNC(1, 128);

        for (int t = 0; t < nf; ++t) {
            if (i < 100) {
                const float am = sh_a[cur][2 * i];       // old alpha[l0-1]
                const float a0 = sh_a[cur][2 * i + 1];   // old alpha[l0]
                const float a1 = sh_a[cur][2 * i + 2];   // old alpha[l1]

                const float h0 = fmaxf(a0, am), l0v = fminf(a0, am);
                const float nv0 = h0 + __logf(1.0f + __expf(l0v - h0)) + lpA;
                const float h1 = fmaxf(a1, a0), l1v = fminf(a1, a0);
                const float nv1 = h1 + __logf(1.0f + __expf(l1v - h1)) + lpB;

                const int   tn = (t + 2 < TT) ? (t + 2) : (TT - 1);
                const float pA = __ldg(lpb0 + (long long)tn * FF);
                const float pB = __ldg(lpb1 + (long long)tn * FF);

                sh_a[cur ^ 1][2 * i + 1] = nv0;
                sh_a[cur ^ 1][2 * i + 2] = nv1;
                if (i == 0) sh_a[cur ^ 1][0] = NEGF;     // alpha[0] = NEG each step
                lpA = lpA1; lpA1 = pA;
                lpB = lpB1; lpB1 = pB;
            }
            BAR_SYNC(1, 128);
            cur ^= 1;
        }
        if (i == 0) g_num[n] = sh_a[cur][qi];
    }
}

__global__ void mmi_finalize(const int* __restrict__ sup, float* __restrict__ out)
{
    const int tid = threadIdx.x;  // 32 threads
    float tot = 0.f, fr = 0.f, af = 0.f;
    if (tid < NN) {
        const int nf = sup[tid * 3 + 2];
        const float t = g_num[tid] - g_den[tid];
        const bool fin = isfinite(t) && (t > 0.5f * NEGF);
        tot = fin ? t : 0.f;
        fr  = fin ? (float)nf : 0.f;
        af  = (float)nf;
    }
    #pragma unroll
    for (int o = 16; o; o >>= 1) {
        tot += __shfl_xor_sync(0xffffffffu, tot, o);
        fr  += __shfl_xor_sync(0xffffffffu, fr, o);
        af  += __shfl_xor_sync(0xffffffffu, af, o);
    }
    if (tid == 0) {
        out[0] = tot;
        out[1] = fr;
        out[2] = af;
    }
}

extern "C" void kernel_launch(void* const* d_in, const int* in_sizes, int n_in,
                              void* d_out, int out_size)
{
    const float* nnet  = (const float*)d_in[0];
    const int*   sup   = (const int*)  d_in[1];
    const float* trans = (const float*)d_in[2];
    const int*   dlab  = (const int*)  d_in[3];
    const int*   nlab  = (const int*)  d_in[4];
    const int*   nlens = (const int*)  d_in[5];

    mmi_forward<<<24, 256>>>(nnet, sup, trans, dlab, nlab, nlens);
    mmi_finalize<<<1, 32>>>(sup, (float*)d_out);
}

// round 12
// speedup vs baseline: 1.4724x; 1.4724x over previous
#include <cuda_runtime.h>
#include <cstdint>
#include <math.h>

#define NN 16
#define TT 800
#define FF 90
#define SS 128
#define LL 200
#define NEGF (-1e30f)

// per-utterance scores scratch (device globals: no allocation allowed)
__device__ float g_den[NN];
__device__ float g_num[NN];

// ---- packed fp32x2 helpers (sm_103a) ----
__device__ __forceinline__ unsigned long long fma_f32x2(unsigned long long a,
                                                        unsigned long long b,
                                                        unsigned long long c) {
    unsigned long long d;
    asm("fma.rn.f32x2 %0, %1, %2, %3;" : "=l"(d) : "l"(a), "l"(b), "l"(c));
    return d;
}
__device__ __forceinline__ unsigned long long add_f32x2(unsigned long long a,
                                                        unsigned long long b) {
    unsigned long long d;
    asm("add.rn.f32x2 %0, %1, %2;" : "=l"(d) : "l"(a), "l"(b));
    return d;
}
__device__ __forceinline__ unsigned long long pack2(float lo, float hi) {
    unsigned long long d;
    asm("mov.b64 %0, {%1, %2};" : "=l"(d) : "f"(lo), "f"(hi));
    return d;
}
__device__ __forceinline__ float2 unpack2(unsigned long long v) {
    float lo, hi;
    asm("mov.b64 {%0, %1}, %2;" : "=f"(lo), "=f"(hi) : "l"(v));
    return make_float2(lo, hi);
}

// blocks 0..15:  den for utterance b. 128 threads, one full state column per
//                thread (no SHFL; 4-warp barrier). ONE warp per SMSP — the
//                128-reg E2 layout does not tolerate a second resident warp.
// blocks 16..31: num for utterance b-16. 128 threads, 2 chain states/thread.
__global__ __launch_bounds__(128, 1)
void mmi_forward(const float* __restrict__ nnet,   // [N, T, F] log-softmax
                 const int*   __restrict__ sup,    // [N, 3]
                 const float* __restrict__ trans,  // [S, S]
                 const int*   __restrict__ dlab,   // [S]
                 const int*   __restrict__ nlab,   // [N, L]
                 const int*   __restrict__ nlens)  // [N]
{
    __shared__ __align__(16) float sh_v[2][SS];
    __shared__ float sh_wsum[4];
    __shared__ float sh_a[2][LL + 8];

    const int tid = threadIdx.x;
    const int b   = blockIdx.x;

    if (b < NN) {
        // ======= denominator forward (scaled linear space), 1 state/thread ====
        const int n  = b;
        const int nf = sup[n * 3 + 2];
        const int s  = tid;                 // output state

        // Full E column (128 k-values) in registers, packed f32x2 (128 regs).
        unsigned long long E2[64];
        #pragma unroll 8
        for (int j = 0; j < 64; ++j) {
            E2[j] = pack2(expf(trans[(2 * j) * SS + s]),
                          expf(trans[(2 * j + 1) * SS + s]));
        }
        const int lab = dlab[s];
        const float* lp_base = nnet + (long long)n * TT * FF + lab;
        float lp  = __ldg(lp_base);                          // t = 0
        float lp1 = __ldg(lp_base + FF);                     // t = 1

        sh_v[0][s] = (s == 0) ? 1.0f : 0.0f;
        __syncthreads();

        int cur  = 0;
        int Mexp = 0;

        #pragma unroll 4
        for (int t = 0; t < nf; ++t) {
            // exact 2^-e rescale keyed to v[0]'s exponent, every 4th step only
            // (parity static inside the unrolled body; 3 unscaled steps drift
            //  at most ~1e13 up / 1e-18 down — far inside fp32 range)
            float ps;
            if ((t & 3) == 0) {
                const float v0 = sh_v[cur][0];
                const int   eb = (int)(__float_as_uint(v0) >> 23);  // biased exp
                Mexp += eb - 127;
                ps = __expf(lp) *
                     __uint_as_float((unsigned)(254 - eb) << 23);
            } else {
                ps = __expf(lp);
            }

            const int   tn   = (t + 2 < TT) ? (t + 2) : (TT - 1);
            const float lpn2 = __ldg(lp_base + (long long)tn * FF); // prefetch d=2

            const ulonglong2* vp =
                reinterpret_cast<const ulonglong2*>(&sh_v[cur][0]);

            // 64 FFMA2 across 4 accumulators, q loaded in 2 chunks of 16
            unsigned long long a0 = 0ull, a1 = 0ull, a2 = 0ull, a3 = 0ull;
            #pragma unroll
            for (int g = 0; g < 2; ++g) {
                ulonglong2 q[16];
                #pragma unroll
                for (int i = 0; i < 16; ++i) q[i] = vp[16 * g + i];
                #pragma unroll
                for (int i = 0; i < 8; ++i) {
                    a0 = fma_f32x2(q[2 * i].x,     E2[32 * g + 4 * i + 0], a0);
                    a1 = fma_f32x2(q[2 * i].y,     E2[32 * g + 4 * i + 1], a1);
                    a2 = fma_f32x2(q[2 * i + 1].x, E2[32 * g + 4 * i + 2], a2);
                    a3 = fma_f32x2(q[2 * i + 1].y, E2[32 * g + 4 * i + 3], a3);
                }
            }
            a0 = add_f32x2(a0, a2);
            a1 = add_f32x2(a1, a3);
            a0 = add_f32x2(a0, a1);
            const float2 u = unpack2(a0);
            const float dot = u.x + u.y;

            sh_v[cur ^ 1][s] = dot * ps;
            lp  = lp1;
            lp1 = lpn2;
            __syncthreads();
            cur ^= 1;
        }

        // den = Mexp*ln2 + log(sum v)
        {
            float v = sh_v[cur][s];
            #pragma unroll
            for (int o = 16; o; o >>= 1) v += __shfl_xor_sync(0xffffffffu, v, o);
            if ((tid & 31) == 0) sh_wsum[tid >> 5] = v;
        }
        __syncthreads();
        if (tid == 0) {
            const float sv = sh_wsum[0] + sh_wsum[1] + sh_wsum[2] + sh_wsum[3];
            g_den[n] = (float)((double)Mexp * 0.6931471805599453 +
                               (double)logf(sv));
        }
    } else {
        // ============ numerator forward (log space), 2 states/thread ==========
        const int n  = b - NN;
        const int nf = sup[n * 3 + 2];
        const int qi = nlens[n];
        const int i  = tid;                 // 0..127; active i < 100

        // thread i owns states l0 = 2i+1 and l1 = 2i+2
        const float* lpb0 = nnet;  // dummy init
        const float* lpb1 = nnet;
        float lpA = 0.f, lpA1 = 0.f, lpB = 0.f, lpB1 = 0.f;

        if (i < 100) {
            const long long base = (long long)n * TT * FF;
            lpb0 = nnet + base + nlab[n * LL + 2 * i];       // emit for l0
            lpb1 = nnet + base + nlab[n * LL + 2 * i + 1];   // emit for l1
            lpA  = __ldg(lpb0);       lpB  = __ldg(lpb1);
            lpA1 = __ldg(lpb0 + FF);  lpB1 = __ldg(lpb1 + FF);
        }
        for (int j = i; j <= LL; j += 128) {
            sh_a[0][j] = (j == 0) ? 0.0f : NEGF;
            sh_a[1][j] = NEGF;
        }
        int cur = 0;
        __syncthreads();

        for (int t = 0; t < nf; ++t) {
            if (i < 100) {
                const float am = sh_a[cur][2 * i];       // old alpha[l0-1]
                const float a0 = sh_a[cur][2 * i + 1];   // old alpha[l0]
                const float a1 = sh_a[cur][2 * i + 2];   // old alpha[l1]

                const float h0 = fmaxf(a0, am), l0v = fminf(a0, am);
                const float nv0 = h0 + __logf(1.0f + __expf(l0v - h0)) + lpA;
                const float h1 = fmaxf(a1, a0), l1v = fminf(a1, a0);
                const float nv1 = h1 + __logf(1.0f + __expf(l1v - h1)) + lpB;

                const int   tn = (t + 2 < TT) ? (t + 2) : (TT - 1);
                const float pA = __ldg(lpb0 + (long long)tn * FF);
                const float pB = __ldg(lpb1 + (long long)tn * FF);

                sh_a[cur ^ 1][2 * i + 1] = nv0;
                sh_a[cur ^ 1][2 * i + 2] = nv1;
                if (i == 0) sh_a[cur ^ 1][0] = NEGF;     // alpha[0] = NEG each step
                lpA = lpA1; lpA1 = pA;
                lpB = lpB1; lpB1 = pB;
            }
            __syncthreads();
            cur ^= 1;
        }
        if (i == 0) g_num[n] = sh_a[cur][qi];
    }
}

__global__ void mmi_finalize(const int* __restrict__ sup, float* __restrict__ out)
{
    const int tid = threadIdx.x;  // 32 threads
    float tot = 0.f, fr = 0.f, af = 0.f;
    if (tid < NN) {
        const int nf = sup[tid * 3 + 2];
        const float t = g_num[tid] - g_den[tid];
        const bool fin = isfinite(t) && (t > 0.5f * NEGF);
        tot = fin ? t : 0.f;
        fr  = fin ? (float)nf : 0.f;
        af  = (float)nf;
    }
    #pragma unroll
    for (int o = 16; o; o >>= 1) {
        tot += __shfl_xor_sync(0xffffffffu, tot, o);
        fr  += __shfl_xor_sync(0xffffffffu, fr, o);
        af  += __shfl_xor_sync(0xffffffffu, af, o);
    }
    if (tid == 0) {
        out[0] = tot;
        out[1] = fr;
        out[2] = af;
    }
}

extern "C" void kernel_launch(void* const* d_in, const int* in_sizes, int n_in,
                              void* d_out, int out_size)
{
    const float* nnet  = (const float*)d_in[0];
    const int*   sup   = (const int*)  d_in[1];
    const float* trans = (const float*)d_in[2];
    const int*   dlab  = (const int*)  d_in[3];
    const int*   nlab  = (const int*)  d_in[4];
    const int*   nlens = (const int*)  d_in[5];

    mmi_forward<<<2 * NN, 128>>>(nnet, sup, trans, dlab, nlab, nlens);
    mmi_finalize<<<1, 32>>>(sup, (float*)d_out);
}

// round 13
// speedup vs baseline: 1.4945x; 1.0150x over previous
#include <cuda_runtime.h>
#include <cuda_fp16.h>
#include <cstdint>
#include <math.h>

#define NN 16
#define TT 800
#define FF 90
#define SS 128
#define LL 200
#define NEGF (-1e30f)

// per-utterance scores scratch (device globals: no allocation allowed)
__device__ float g_den[NN];
__device__ float g_num[NN];

// blocks 0..15:  den for utterance b. 128 threads, one full state column per
//                thread, fp16 math (HFMA2 rt=2), delayed block-max-keyed
//                exact power-of-two rescale centered at 2^-3.
// blocks 16..31: num for utterance b-16. 128 threads, 2 chain states/thread.
__global__ __launch_bounds__(128, 1)
void mmi_forward(const float* __restrict__ nnet,   // [N, T, F] log-softmax
                 const int*   __restrict__ sup,    // [N, 3]
                 const float* __restrict__ trans,  // [S, S]
                 const int*   __restrict__ dlab,   // [S]
                 const int*   __restrict__ nlab,   // [N, L]
                 const int*   __restrict__ nlens)  // [N]
{
    __shared__ __align__(16) __half sh_vh[2][SS];   // fp16 state vector
    __shared__ unsigned sh_wmax[2][4];              // per-warp fp32-bit maxes
    __shared__ float sh_wsum[4];
    __shared__ float sh_a[2][LL + 8];

    const int tid = threadIdx.x;
    const int b   = blockIdx.x;

    if (b < NN) {
        // ======= denominator forward (scaled fp16 linear space) ===============
        const int n    = b;
        const int nf   = sup[n * 3 + 2];
        const int s    = tid;               // output state
        const int lane = tid & 31;
        const int wrp  = tid >> 5;

        // Full E column (128 k-values) in fp16, packed half2 (64 regs).
        half2 E2h[64];
        #pragma unroll 8
        for (int j = 0; j < 64; ++j) {
            E2h[j] = __floats2half2_rn(expf(trans[(2 * j) * SS + s]),
                                       expf(trans[(2 * j + 1) * SS + s]));
        }
        const int lab = dlab[s];
        const float* lp_base = nnet + (long long)n * TT * FF + lab;
        float lp  = __ldg(lp_base);                          // t = 0
        float lp1 = __ldg(lp_base + FF);                     // t = 1

        // init: stored v = true v * 2^-3 (center 2^-3); Mexp starts at 3
        sh_vh[0][s] = __float2half_rn((s == 0) ? 0.125f : 0.0f);
        if (tid < 4) {
            sh_wmax[0][tid] = 124u << 23;   // bits of 2^-3 -> first sigma = 1
            sh_wmax[1][tid] = 124u << 23;
        }
        __syncthreads();

        int cur  = 0;
        int Mexp = 3;

        #pragma unroll 2
        for (int t = 0; t < nf; ++t) {
            // delayed block-max rescale: normalize prev step's max to [2^-3,2^-2)
            unsigned m = sh_wmax[cur][0];
            m = max(m, sh_wmax[cur][1]);
            m = max(m, sh_wmax[cur][2]);
            m = max(m, sh_wmax[cur][3]);
            const int   eb    = (int)(m >> 23);
            const float sigma = __uint_as_float((unsigned)(251 - eb) << 23);
            Mexp += eb - 124;
            const float ps = __expf(lp) * sigma;

            const int   tn   = (t + 2 < TT) ? (t + 2) : (TT - 1);
            const float lpn2 = __ldg(lp_base + (long long)tn * FF); // prefetch d=2

            const uint4* vp = reinterpret_cast<const uint4*>(&sh_vh[cur][0]);

            // 64 HFMA2 across 4 half2 accumulators (16 terms per acc per lane)
            half2 a0 = __float2half2_rn(0.f), a1 = a0, a2 = a0, a3 = a0;
            #pragma unroll
            for (int g = 0; g < 2; ++g) {
                uint4 q[8];
                #pragma unroll
                for (int i = 0; i < 8; ++i) q[i] = vp[8 * g + i];
                #pragma unroll
                for (int i = 0; i < 8; ++i) {
                    const int bb = (8 * g + i) * 4;
                    const half2 v0 = *reinterpret_cast<const half2*>(&q[i].x);
                    const half2 v1 = *reinterpret_cast<const half2*>(&q[i].y);
                    const half2 v2 = *reinterpret_cast<const half2*>(&q[i].z);
                    const half2 v3 = *reinterpret_cast<const half2*>(&q[i].w);
                    a0 = __hfma2(v0, E2h[bb + 0], a0);
                    a1 = __hfma2(v1, E2h[bb + 1], a1);
                    a2 = __hfma2(v2, E2h[bb + 2], a2);
                    a3 = __hfma2(v3, E2h[bb + 3], a3);
                }
            }
            const half2 s01 = __hadd2(a0, a1);
            const half2 s23 = __hadd2(a2, a3);
            const half2 sal = __hadd2(s01, s23);
            const float dot = __low2float(sal) + __high2float(sal);

            const float accv = dot * ps;
            // warp max of positive fp32 values (bit compare), for NEXT step
            const unsigned wm =
                __reduce_max_sync(0xffffffffu, __float_as_uint(accv));
            if (lane == 0) sh_wmax[cur ^ 1][wrp] = wm;
            sh_vh[cur ^ 1][s] = __float2half_rn(accv);
            lp  = lp1;
            lp1 = lpn2;
            __syncthreads();
            cur ^= 1;
        }

        // den = Mexp*ln2 + log(sum stored v)
        {
            float v = __half2float(sh_vh[cur][s]);
            #pragma unroll
            for (int o = 16; o; o >>= 1) v += __shfl_xor_sync(0xffffffffu, v, o);
            if (lane == 0) sh_wsum[wrp] = v;
        }
        __syncthreads();
        if (tid == 0) {
            const float sv = sh_wsum[0] + sh_wsum[1] + sh_wsum[2] + sh_wsum[3];
            g_den[n] = (float)((double)Mexp * 0.6931471805599453 +
                               (double)logf(sv));
        }
    } else {
        // ============ numerator forward (log space), 2 states/thread ==========
        const int n  = b - NN;
        const int nf = sup[n * 3 + 2];
        const int qi = nlens[n];
        const int i  = tid;                 // 0..127; active i < 100

        // thread i owns states l0 = 2i+1 and l1 = 2i+2
        const float* lpb0 = nnet;  // dummy init
        const float* lpb1 = nnet;
        float lpA = 0.f, lpA1 = 0.f, lpB = 0.f, lpB1 = 0.f;

        if (i < 100) {
            const long long base = (long long)n * TT * FF;
            lpb0 = nnet + base + nlab[n * LL + 2 * i];       // emit for l0
            lpb1 = nnet + base + nlab[n * LL + 2 * i + 1];   // emit for l1
            lpA  = __ldg(lpb0);       lpB  = __ldg(lpb1);
            lpA1 = __ldg(lpb0 + FF);  lpB1 = __ldg(lpb1 + FF);
        }
        for (int j = i; j <= LL; j += 128) {
            sh_a[0][j] = (j == 0) ? 0.0f : NEGF;
            sh_a[1][j] = NEGF;
        }
        int cur = 0;
        __syncthreads();

        for (int t = 0; t < nf; ++t) {
            if (i < 100) {
                const float am = sh_a[cur][2 * i];       // old alpha[l0-1]
                const float a0 = sh_a[cur][2 * i + 1];   // old alpha[l0]
                const float a1 = sh_a[cur][2 * i + 2];   // old alpha[l1]

                const float h0 = fmaxf(a0, am), l0v = fminf(a0, am);
                const float nv0 = h0 + __logf(1.0f + __expf(l0v - h0)) + lpA;
                const float h1 = fmaxf(a1, a0), l1v = fminf(a1, a0);
                const float nv1 = h1 + __logf(1.0f + __expf(l1v - h1)) + lpB;

                const int   tn = (t + 2 < TT) ? (t + 2) : (TT - 1);
                const float pA = __ldg(lpb0 + (long long)tn * FF);
                const float pB = __ldg(lpb1 + (long long)tn * FF);

                sh_a[cur ^ 1][2 * i + 1] = nv0;
                sh_a[cur ^ 1][2 * i + 2] = nv1;
                if (i == 0) sh_a[cur ^ 1][0] = NEGF;     // alpha[0] = NEG each step
                lpA = lpA1; lpA1 = pA;
                lpB = lpB1; lpB1 = pB;
            }
            __syncthreads();
            cur ^= 1;
        }
        if (i == 0) g_num[n] = sh_a[cur][qi];
    }
}

__global__ void mmi_finalize(const int* __restrict__ sup, float* __restrict__ out)
{
    const int tid = threadIdx.x;  // 32 threads
    float tot = 0.f, fr = 0.f, af = 0.f;
    if (tid < NN) {
        const int nf = sup[tid * 3 + 2];
        const float t = g_num[tid] - g_den[tid];
        const bool fin = isfinite(t) && (t > 0.5f * NEGF);
        tot = fin ? t : 0.f;
        fr  = fin ? (float)nf : 0.f;
        af  = (float)nf;
    }
    #pragma unroll
    for (int o = 16; o; o >>= 1) {
        tot += __shfl_xor_sync(0xffffffffu, tot, o);
        fr  += __shfl_xor_sync(0xffffffffu, fr, o);
        af  += __shfl_xor_sync(0xffffffffu, af, o);
    }
    if (tid == 0) {
        out[0] = tot;
        out[1] = fr;
        out[2] = af;
    }
}

extern "C" void kernel_launch(void* const* d_in, const int* in_sizes, int n_in,
                              void* d_out, int out_size)
{
    const float* nnet  = (const float*)d_in[0];
    const int*   sup   = (const int*)  d_in[1];
    const float* trans = (const float*)d_in[2];
    const int*   dlab  = (const int*)  d_in[3];
    const int*   nlab  = (const int*)  d_in[4];
    const int*   nlens = (const int*)  d_in[5];

    mmi_forward<<<2 * NN, 128>>>(nnet, sup, trans, dlab, nlab, nlens);
    mmi_finalize<<<1, 32>>>(sup, (float*)d_out);
}